// round 3
// baseline (speedup 1.0000x reference)
#include <cuda_runtime.h>
#include <cuda_bf16.h>

// NV12 -> RGB, 4K frame.
// Input d_in[0]: int32, (2160, 3840, 6) flattened:
//   [0 : 7680*4320)            = full-res Y plane (row-major 4320 x 7680)
//   [7680*4320 : end)          = interleaved UV at half-res (2160 x 3840 x 2)
// d_in[1]: float32[9]  yuv_to_rgb matrix, row-major (3,3)
// d_in[2]: float32[3]  yuv_to_rgb_offset
// Output: float32 (2160, 3840, 3):  rgb[j] = sum_i (yuv[i]-off[i]) * M[i][j]
// where yuv = [Y[2r,2c], U[r,c], V[r,c]].

#define HH 2160
#define HW 3840
#define FULL_W (HW * 2)            // 7680
#define FULL_H (HH * 2)            // 4320
#define Y_ELEMS (FULL_W * FULL_H)  // 33177600
#define NPAIRS (HH * (HW / 2))     // 4147200

__global__ __launch_bounds__(256)
void nv12_to_rgb_kernel(const int* __restrict__ data,
                        const float* __restrict__ M,
                        const float* __restrict__ off,
                        float* __restrict__ out)
{
    int idx = blockIdx.x * blockDim.x + threadIdx.x;  // pair index
    if (idx >= NPAIRS) return;

    int r  = idx / (HW / 2);
    int cp = idx - r * (HW / 2);
    int c  = cp * 2;  // even column in half-res grid

    // Y: full-res row 2r, cols 2c .. 2c+3 (use 2c and 2c+2). 16B-aligned.
    const int4 yv = *reinterpret_cast<const int4*>(data + (2 * r) * FULL_W + 2 * c);
    // UV: interleaved, 4 consecutive ints = u0,v0,u1,v1. 16B-aligned.
    const int4 uv = *reinterpret_cast<const int4*>(data + Y_ELEMS + (r * HW + c) * 2);

    // Matrix + offset: uniform addresses -> L1 broadcast.
    const float m00 = __ldg(M + 0), m01 = __ldg(M + 1), m02 = __ldg(M + 2);
    const float m10 = __ldg(M + 3), m11 = __ldg(M + 4), m12 = __ldg(M + 5);
    const float m20 = __ldg(M + 6), m21 = __ldg(M + 7), m22 = __ldg(M + 8);
    const float o0 = __ldg(off + 0), o1 = __ldg(off + 1), o2 = __ldg(off + 2);

    // pixel 0
    float y0 = (float)yv.x - o0;
    float u0 = (float)uv.x - o1;
    float v0 = (float)uv.y - o2;
    float r0 = y0 * m00 + u0 * m10 + v0 * m20;
    float g0 = y0 * m01 + u0 * m11 + v0 * m21;
    float b0 = y0 * m02 + u0 * m12 + v0 * m22;

    // pixel 1
    float y1 = (float)yv.z - o0;
    float u1 = (float)uv.z - o1;
    float v1 = (float)uv.w - o2;
    float r1 = y1 * m00 + u1 * m10 + v1 * m20;
    float g1 = y1 * m01 + u1 * m11 + v1 * m21;
    float b1 = y1 * m02 + u1 * m12 + v1 * m22;

    // 6 consecutive floats at out + (r*HW + c)*3; base is even -> 8B aligned.
    float* o = out + (r * HW + c) * 3;
    reinterpret_cast<float2*>(o)[0] = make_float2(r0, g0);
    reinterpret_cast<float2*>(o)[1] = make_float2(b0, r1);
    reinterpret_cast<float2*>(o)[2] = make_float2(g1, b1);
}

extern "C" void kernel_launch(void* const* d_in, const int* in_sizes, int n_in,
                              void* d_out, int out_size)
{
    const int*   data = (const int*)d_in[0];
    const float* M    = (const float*)d_in[1];
    const float* off  = (const float*)d_in[2];
    float*       out  = (float*)d_out;

    const int threads = 256;
    const int blocks  = (NPAIRS + threads - 1) / threads;
    nv12_to_rgb_kernel<<<blocks, threads>>>(data, M, off, out);
}